// round 9
// baseline (speedup 1.0000x reference)
#include <cuda_runtime.h>
#include <cuda_bf16.h>

// Problem constants (fixed shapes per reference setup_inputs)
#define D 512
#define T 50000
#define K 16
#define N_ITERS 10

// Heavy-kernel tiling
#define HK_THREADS 256
#define CPT 4                       // columns per thread (2x f32x2 accumulators)
#define TILE_COLS (HK_THREADS*CPT)  // 1024
#define NTILE 49                    // ceil(50000/1024)
#define CHUNK_ROWS 32
#define NCHUNK 16                   // 16*32 = 512 rows

// Reference hyper-parameters, reproduced with python-double -> float semantics
#define LAMBDA1_F 0.3366f
#define SHRINK_C ((float)(0.1 * 0.3366))        // LR*LAMBDA1
#define BETA1_F 0.9f
#define BETA2_F 0.999f
#define ONE_M_B1 ((float)(1.0 - 0.9))
#define ONE_M_B2 ((float)(1.0 - 0.999))
#define ADAM_EPS_F 1e-8f
#define LR_F 0.1f

// Device-global scratch (no allocations allowed)
__device__ float g_B[D * K];      // B used by the loss this iteration (P for it=1, shrink(P) after)
__device__ float g_P[D * K];      // raw Adam parameter
__device__ float g_M[D * K];
__device__ float g_V[D * K];
__device__ float g_colsum[T];     // per-column abs sums (atomicAdd accumulated)

// ---------- f32x2 helpers ----------
__device__ __forceinline__ unsigned long long fma2(unsigned long long a,
                                                   unsigned long long b,
                                                   unsigned long long c) {
    unsigned long long d;
    asm("fma.rn.f32x2 %0, %1, %2, %3;" : "=l"(d) : "l"(a), "l"(b), "l"(c));
    return d;
}
__device__ __forceinline__ unsigned long long add2(unsigned long long a,
                                                   unsigned long long b) {
    unsigned long long d;
    asm("add.rn.f32x2 %0, %1, %2;" : "=l"(d) : "l"(a), "l"(b));
    return d;
}
__device__ __forceinline__ float f2lo(unsigned long long x) {
    return __uint_as_float((unsigned int)x);
}
__device__ __forceinline__ float f2hi(unsigned long long x) {
    return __uint_as_float((unsigned int)(x >> 32));
}
__device__ __forceinline__ float sgnf(float x) {
    return (float)((x > 0.0f) - (x < 0.0f));
}

// ---------- init ----------
__global__ void init_kernel(const float* __restrict__ Binit) {
    int i = blockIdx.x * blockDim.x + threadIdx.x;
    if (i < T) g_colsum[i] = 0.0f;
    if (i < D * K) {
        float b = Binit[i];
        g_P[i] = b;
        g_B[i] = b;     // iteration 1 loss sees raw P
        g_M[i] = 0.0f;
        g_V[i] = 0.0f;
    }
}

// ---------- heavy: colsum[j] += sum_i |E[i,j] - sum_k B[i,k]*A[k,j]| over a row chunk ----------
__global__ __launch_bounds__(HK_THREADS, 2)
void heavy_kernel(const float* __restrict__ E, const float* __restrict__ A) {
    __shared__ unsigned long long sB[CHUNK_ROWS * K];   // -B duplicated into both f32x2 lanes

    const int tile = blockIdx.x;
    const int chunk = blockIdx.y;
    const int tid = threadIdx.x;

    // load this chunk's B rows, negated + lane-duplicated
    for (int idx = tid; idx < CHUNK_ROWS * K; idx += HK_THREADS) {
        int r = idx >> 4;
        int k = idx & 15;
        float b = -g_B[(chunk * CHUNK_ROWS + r) * K + k];
        unsigned int ub = __float_as_uint(b);
        sB[idx] = ((unsigned long long)ub << 32) | (unsigned long long)ub;
    }
    __syncthreads();

    const int j0 = tile * TILE_COLS + tid * CPT;
    if (j0 >= T) return;                 // tail tile; no further syncs

    // A[k, j0..j0+3] into registers (16B aligned: k*T and j0 are multiples of 4)
    unsigned long long a01[K], a23[K];
#pragma unroll
    for (int k = 0; k < K; k++) {
        ulonglong2 av = *reinterpret_cast<const ulonglong2*>(A + k * T + j0);
        a01[k] = av.x;
        a23[k] = av.y;
    }

    unsigned long long cs01 = 0ull, cs23 = 0ull;        // packed (0.0f, 0.0f)
    const float* Erow = E + (chunk * CHUNK_ROWS) * T + j0;

#pragma unroll 4
    for (int r = 0; r < CHUNK_ROWS; r++) {
        ulonglong2 ev = *reinterpret_cast<const ulonglong2*>(Erow);
        Erow += T;
        unsigned long long acc01 = ev.x;
        unsigned long long acc23 = ev.y;
#pragma unroll
        for (int k = 0; k < K; k++) {
            unsigned long long b = sB[r * K + k];
            acc01 = fma2(b, a01[k], acc01);
            acc23 = fma2(b, a23[k], acc23);
        }
        cs01 = add2(cs01, acc01 & 0x7FFFFFFF7FFFFFFFull);
        cs23 = add2(cs23, acc23 & 0x7FFFFFFF7FFFFFFFull);
    }

    atomicAdd(&g_colsum[j0 + 0], f2lo(cs01));
    atomicAdd(&g_colsum[j0 + 1], f2hi(cs01));
    atomicAdd(&g_colsum[j0 + 2], f2lo(cs23));
    atomicAdd(&g_colsum[j0 + 3], f2hi(cs23));
}

// ---------- update: argmax j*, argmax k*, rank-1 gradient, shrink-chain, Adam ----------
__global__ void update_kernel(const float* __restrict__ E, const float* __restrict__ A,
                              float* __restrict__ outB, int it) {
    __shared__ unsigned long long warpmax[32];
    __shared__ float sA[K];
    __shared__ float sColabs[K];
    __shared__ int sJstar, sKstar;

    const int tid = threadIdx.x;

    // Phase 1: argmax over colsum (and reset colsum for next iteration)
    unsigned long long best = 0ull;
    for (int j = tid; j < T; j += 1024) {
        float v = g_colsum[j];
        g_colsum[j] = 0.0f;
        // v >= 0 so float bits are order-preserving; tie-break toward smaller j
        unsigned long long key =
            ((unsigned long long)__float_as_uint(v) << 32) | (unsigned int)(T - 1 - j);
        if (key > best) best = key;
    }
#pragma unroll
    for (int o = 16; o; o >>= 1) {
        unsigned long long other = __shfl_down_sync(0xffffffffu, best, o);
        if (other > best) best = other;
    }
    if ((tid & 31) == 0) warpmax[tid >> 5] = best;
    __syncthreads();
    if (tid < 32) {
        unsigned long long b = warpmax[tid];
#pragma unroll
        for (int o = 16; o; o >>= 1) {
            unsigned long long other = __shfl_down_sync(0xffffffffu, b, o);
            if (other > b) b = other;
        }
        if (tid == 0) sJstar = T - 1 - (int)(b & 0xffffffffu);
    }
    __syncthreads();
    const int jstar = sJstar;

    // Phase 2a: stage A[:, j*] into smem
    if (tid < K) sA[tid] = A[tid * T + jstar];

    // Phase 3: column-abs-sums of B (16 warps, one column each)
    {
        int w = tid >> 5, lane = tid & 31;
        if (w < K) {
            float s = 0.0f;
            for (int i = lane; i < D; i += 32) s += fabsf(g_B[i * K + w]);
#pragma unroll
            for (int o = 16; o; o >>= 1) s += __shfl_down_sync(0xffffffffu, s, o);
            if (lane == 0) sColabs[w] = s;
        }
    }
    __syncthreads();
    if (tid == 0) {
        int ks = 0;
        float bv = sColabs[0];
#pragma unroll
        for (int k = 1; k < K; k++)
            if (sColabs[k] > bv) { bv = sColabs[k]; ks = k; }
        sKstar = ks;
    }

    // Phase 2b: residual sign for row tid at column j* (exact fp32)
    float si = 0.0f;
    if (tid < D) {
        float r = E[tid * T + jstar];
#pragma unroll
        for (int k = 0; k < K; k++) r -= g_B[tid * K + k] * sA[k];
        si = sgnf(r);
    }
    __syncthreads();            // sKstar ready; all reads of g_B complete before writes below
    const int kstar = sKstar;

    // Phase 4: gradient + shrink chain + Adam + write new B = shrink(P)
    if (tid < D) {
        float tf = (float)it;
        float bc1 = 1.0f - powf(BETA1_F, tf);
        float bc2 = 1.0f - powf(BETA2_F, tf);
#pragma unroll
        for (int k = 0; k < K; k++) {
            int idx = tid * K + k;
            float bu = g_B[idx];                      // B the loss saw this iteration
            float g = -si * sA[k];
            if (k == kstar) g += LAMBDA1_F * sgnf(bu);
            float p = g_P[idx];
            if (it >= 2) g *= sgnf(p) * sgnf(p - SHRINK_C);   // d shrink / dP
            float m = BETA1_F * g_M[idx] + ONE_M_B1 * g;
            float v = BETA2_F * g_V[idx] + ONE_M_B2 * g * g;
            g_M[idx] = m;
            g_V[idx] = v;
            float mh = m / bc1;
            float vh = v / bc2;
            p = p - LR_F * mh / (sqrtf(vh) + ADAM_EPS_F);
            g_P[idx] = p;
            float bn = sgnf(p) * fmaxf(0.0f, fabsf(p - SHRINK_C));
            g_B[idx] = bn;                            // loss for next iteration sees shrink(P)
            if (it == N_ITERS) outB[idx] = bn;        // final output basis
        }
    }
}

extern "C" void kernel_launch(void* const* d_in, const int* in_sizes, int n_in,
                              void* d_out, int out_size) {
    (void)in_sizes; (void)n_in; (void)out_size;
    const float* E  = (const float*)d_in[0];   // embedding (512, 50000)
    const float* B0 = (const float*)d_in[1];   // basis_init (512, 16)
    const float* A  = (const float*)d_in[2];   // activation_init (16, 50000)
    float* out = (float*)d_out;                // [shrink(P) (512x16) | A (16x50000)]

    // A is constant in the reference (optimizer_act never steps) — copy once
    cudaMemcpyAsync(out + D * K, (const void*)A, (size_t)K * T * sizeof(float),
                    cudaMemcpyDeviceToDevice);

    init_kernel<<<(T + 255) / 256, 256>>>(B0);

    dim3 grid(NTILE, NCHUNK);
    for (int it = 1; it <= N_ITERS; ++it) {
        heavy_kernel<<<grid, HK_THREADS>>>(E, A);
        update_kernel<<<1, 1024>>>(E, A, out, it);
    }
}

// round 10
// speedup vs baseline: 1.0012x; 1.0012x over previous
#include <cuda_runtime.h>
#include <cuda_bf16.h>

// Problem constants (fixed shapes per reference setup_inputs)
#define D 512
#define T 50000
#define K 16
#define N_ITERS 10

// Heavy-kernel tiling
#define HK_THREADS 256
#define CPT 4                       // columns per thread (2x f32x2 accumulators)
#define TILE_COLS (HK_THREADS*CPT)  // 1024
#define NTILE 49                    // ceil(50000/1024)
#define CHUNK_ROWS 32
#define NCHUNK 16                   // 16*32 = 512 rows

// Reference hyper-parameters, reproduced with python-double -> float semantics
#define LAMBDA1_F 0.3366f
#define SHRINK_C ((float)(0.1 * 0.3366))        // LR*LAMBDA1
#define BETA1_F 0.9f
#define BETA2_F 0.999f
#define ONE_M_B1 ((float)(1.0 - 0.9))
#define ONE_M_B2 ((float)(1.0 - 0.999))
#define ADAM_EPS_F 1e-8f
#define LR_F 0.1f

// Device-global scratch (no allocations allowed)
__device__ float g_B[D * K];      // B used by the loss this iteration (P for it=1, shrink(P) after)
__device__ float g_P[D * K];      // raw Adam parameter
__device__ float g_M[D * K];
__device__ float g_V[D * K];
__device__ float g_colsum[T];     // per-column abs sums (atomicAdd accumulated)

// ---------- f32x2 helpers ----------
__device__ __forceinline__ unsigned long long fma2(unsigned long long a,
                                                   unsigned long long b,
                                                   unsigned long long c) {
    unsigned long long d;
    asm("fma.rn.f32x2 %0, %1, %2, %3;" : "=l"(d) : "l"(a), "l"(b), "l"(c));
    return d;
}
__device__ __forceinline__ unsigned long long add2(unsigned long long a,
                                                   unsigned long long b) {
    unsigned long long d;
    asm("add.rn.f32x2 %0, %1, %2;" : "=l"(d) : "l"(a), "l"(b));
    return d;
}
__device__ __forceinline__ float f2lo(unsigned long long x) {
    return __uint_as_float((unsigned int)x);
}
__device__ __forceinline__ float f2hi(unsigned long long x) {
    return __uint_as_float((unsigned int)(x >> 32));
}
__device__ __forceinline__ float sgnf(float x) {
    return (float)((x > 0.0f) - (x < 0.0f));
}

// ---------- init ----------
__global__ void init_kernel(const float* __restrict__ Binit) {
    int i = blockIdx.x * blockDim.x + threadIdx.x;
    if (i < T) g_colsum[i] = 0.0f;
    if (i < D * K) {
        float b = Binit[i];
        g_P[i] = b;
        g_B[i] = b;     // iteration 1 loss sees raw P
        g_M[i] = 0.0f;
        g_V[i] = 0.0f;
    }
}

// ---------- heavy: colsum[j] += sum_i |E[i,j] - sum_k B[i,k]*A[k,j]| over a row chunk ----------
__global__ __launch_bounds__(HK_THREADS, 2)
void heavy_kernel(const float* __restrict__ E, const float* __restrict__ A) {
    __shared__ unsigned long long sB[CHUNK_ROWS * K];   // -B duplicated into both f32x2 lanes

    const int tile = blockIdx.x;
    const int chunk = blockIdx.y;
    const int tid = threadIdx.x;

    // load this chunk's B rows, negated + lane-duplicated
    for (int idx = tid; idx < CHUNK_ROWS * K; idx += HK_THREADS) {
        int r = idx >> 4;
        int k = idx & 15;
        float b = -g_B[(chunk * CHUNK_ROWS + r) * K + k];
        unsigned int ub = __float_as_uint(b);
        sB[idx] = ((unsigned long long)ub << 32) | (unsigned long long)ub;
    }
    __syncthreads();

    const int j0 = tile * TILE_COLS + tid * CPT;
    if (j0 >= T) return;                 // tail tile; no further syncs

    // A[k, j0..j0+3] into registers (16B aligned: k*T and j0 are multiples of 4)
    unsigned long long a01[K], a23[K];
#pragma unroll
    for (int k = 0; k < K; k++) {
        ulonglong2 av = *reinterpret_cast<const ulonglong2*>(A + k * T + j0);
        a01[k] = av.x;
        a23[k] = av.y;
    }

    unsigned long long cs01 = 0ull, cs23 = 0ull;        // packed (0.0f, 0.0f)
    const float* Erow = E + (chunk * CHUNK_ROWS) * T + j0;

#pragma unroll 4
    for (int r = 0; r < CHUNK_ROWS; r++) {
        ulonglong2 ev = *reinterpret_cast<const ulonglong2*>(Erow);
        Erow += T;
        unsigned long long acc01 = ev.x;
        unsigned long long acc23 = ev.y;
#pragma unroll
        for (int k = 0; k < K; k++) {
            unsigned long long b = sB[r * K + k];
            acc01 = fma2(b, a01[k], acc01);
            acc23 = fma2(b, a23[k], acc23);
        }
        cs01 = add2(cs01, acc01 & 0x7FFFFFFF7FFFFFFFull);
        cs23 = add2(cs23, acc23 & 0x7FFFFFFF7FFFFFFFull);
    }

    atomicAdd(&g_colsum[j0 + 0], f2lo(cs01));
    atomicAdd(&g_colsum[j0 + 1], f2hi(cs01));
    atomicAdd(&g_colsum[j0 + 2], f2lo(cs23));
    atomicAdd(&g_colsum[j0 + 3], f2hi(cs23));
}

// ---------- update: argmax j*, argmax k*, rank-1 gradient, shrink-chain, Adam ----------
__global__ void update_kernel(const float* __restrict__ E, const float* __restrict__ A,
                              float* __restrict__ outB, int it) {
    __shared__ unsigned long long warpmax[32];
    __shared__ float sA[K];
    __shared__ float sColabs[K];
    __shared__ int sJstar, sKstar;

    const int tid = threadIdx.x;

    // Phase 1: argmax over colsum (and reset colsum for next iteration)
    unsigned long long best = 0ull;
    for (int j = tid; j < T; j += 1024) {
        float v = g_colsum[j];
        g_colsum[j] = 0.0f;
        // v >= 0 so float bits are order-preserving; tie-break toward smaller j
        unsigned long long key =
            ((unsigned long long)__float_as_uint(v) << 32) | (unsigned int)(T - 1 - j);
        if (key > best) best = key;
    }
#pragma unroll
    for (int o = 16; o; o >>= 1) {
        unsigned long long other = __shfl_down_sync(0xffffffffu, best, o);
        if (other > best) best = other;
    }
    if ((tid & 31) == 0) warpmax[tid >> 5] = best;
    __syncthreads();
    if (tid < 32) {
        unsigned long long b = warpmax[tid];
#pragma unroll
        for (int o = 16; o; o >>= 1) {
            unsigned long long other = __shfl_down_sync(0xffffffffu, b, o);
            if (other > b) b = other;
        }
        if (tid == 0) sJstar = T - 1 - (int)(b & 0xffffffffu);
    }
    __syncthreads();
    const int jstar = sJstar;

    // Phase 2a: stage A[:, j*] into smem
    if (tid < K) sA[tid] = A[tid * T + jstar];

    // Phase 3: column-abs-sums of B (16 warps, one column each)
    {
        int w = tid >> 5, lane = tid & 31;
        if (w < K) {
            float s = 0.0f;
            for (int i = lane; i < D; i += 32) s += fabsf(g_B[i * K + w]);
#pragma unroll
            for (int o = 16; o; o >>= 1) s += __shfl_down_sync(0xffffffffu, s, o);
            if (lane == 0) sColabs[w] = s;
        }
    }
    __syncthreads();
    if (tid == 0) {
        int ks = 0;
        float bv = sColabs[0];
#pragma unroll
        for (int k = 1; k < K; k++)
            if (sColabs[k] > bv) { bv = sColabs[k]; ks = k; }
        sKstar = ks;
    }

    // Phase 2b: residual sign for row tid at column j* (exact fp32)
    float si = 0.0f;
    if (tid < D) {
        float r = E[tid * T + jstar];
#pragma unroll
        for (int k = 0; k < K; k++) r -= g_B[tid * K + k] * sA[k];
        si = sgnf(r);
    }
    __syncthreads();            // sKstar ready; all reads of g_B complete before writes below
    const int kstar = sKstar;

    // Phase 4: gradient + shrink chain + Adam + write new B = shrink(P)
    if (tid < D) {
        float tf = (float)it;
        float bc1 = 1.0f - powf(BETA1_F, tf);
        float bc2 = 1.0f - powf(BETA2_F, tf);
#pragma unroll
        for (int k = 0; k < K; k++) {
            int idx = tid * K + k;
            float bu = g_B[idx];                      // B the loss saw this iteration
            float g = -si * sA[k];
            if (k == kstar) g += LAMBDA1_F * sgnf(bu);
            float p = g_P[idx];
            if (it >= 2) g *= sgnf(p) * sgnf(p - SHRINK_C);   // d shrink / dP
            float m = BETA1_F * g_M[idx] + ONE_M_B1 * g;
            float v = BETA2_F * g_V[idx] + ONE_M_B2 * g * g;
            g_M[idx] = m;
            g_V[idx] = v;
            float mh = m / bc1;
            float vh = v / bc2;
            p = p - LR_F * mh / (sqrtf(vh) + ADAM_EPS_F);
            g_P[idx] = p;
            float bn = sgnf(p) * fmaxf(0.0f, fabsf(p - SHRINK_C));
            g_B[idx] = bn;                            // loss for next iteration sees shrink(P)
            if (it == N_ITERS) outB[idx] = bn;        // final output basis
        }
    }
}

extern "C" void kernel_launch(void* const* d_in, const int* in_sizes, int n_in,
                              void* d_out, int out_size) {
    (void)in_sizes; (void)n_in; (void)out_size;
    const float* E  = (const float*)d_in[0];   // embedding (512, 50000)
    const float* B0 = (const float*)d_in[1];   // basis_init (512, 16)
    const float* A  = (const float*)d_in[2];   // activation_init (16, 50000)
    float* out = (float*)d_out;                // [shrink(P) (512x16) | A (16x50000)]

    // A is constant in the reference (optimizer_act never steps) — copy once
    cudaMemcpyAsync(out + D * K, (const void*)A, (size_t)K * T * sizeof(float),
                    cudaMemcpyDeviceToDevice);

    init_kernel<<<(T + 255) / 256, 256>>>(B0);

    dim3 grid(NTILE, NCHUNK);
    for (int it = 1; it <= N_ITERS; ++it) {
        heavy_kernel<<<grid, HK_THREADS>>>(E, A);
        update_kernel<<<1, 1024>>>(E, A, out, it);
    }
}

// round 11
// speedup vs baseline: 1.1142x; 1.1129x over previous
#include <cuda_runtime.h>
#include <cuda_bf16.h>

// Problem constants (fixed shapes per reference setup_inputs)
#define D 512
#define T 50000
#define K 16
#define N_ITERS 10

// Heavy-kernel tiling
#define HK_THREADS 256
#define CPT 4                       // columns per thread (2x f32x2 accumulators)
#define TILE_COLS (HK_THREADS*CPT)  // 1024
#define NTILE 49                    // ceil(50000/1024)
#define CHUNK_ROWS 32
#define NCHUNK 16                   // 16*32 = 512 rows

// Argmax+update kernel
#define AX_THREADS 512
#define AX_CPT 2
#define AX_BLOCKS 50                // 50*512*2 = 51200 >= 50000

// Reference hyper-parameters
#define LAMBDA1_F 0.3366f
#define SHRINK_C ((float)(0.1 * 0.3366))        // LR*LAMBDA1
#define BETA1_F 0.9f
#define BETA2_F 0.999f
#define ONE_M_B1 ((float)(1.0 - 0.9))
#define ONE_M_B2 ((float)(1.0 - 0.999))
#define ADAM_EPS_F 1e-8f
#define LR_F 0.1f

// Device-global scratch (no allocations allowed)
__device__ float g_B[D * K];      // B the loss sees (P for it=1, shrink(P) after)
__device__ float g_P[D * K];
__device__ float g_M[D * K];
__device__ float g_V[D * K];
__device__ float g_part[NCHUNK * T];              // per-chunk column partial sums
__device__ __nv_bfloat16 g_Ebf[(size_t)D * T];    // bf16 copy of E (iters 2..N)
__device__ unsigned long long g_best[N_ITERS + 1];
__device__ unsigned int g_count[N_ITERS + 1];

// ---------- f32x2 helpers ----------
__device__ __forceinline__ unsigned long long fma2(unsigned long long a,
                                                   unsigned long long b,
                                                   unsigned long long c) {
    unsigned long long d;
    asm("fma.rn.f32x2 %0, %1, %2, %3;" : "=l"(d) : "l"(a), "l"(b), "l"(c));
    return d;
}
__device__ __forceinline__ unsigned long long add2(unsigned long long a,
                                                   unsigned long long b) {
    unsigned long long d;
    asm("add.rn.f32x2 %0, %1, %2;" : "=l"(d) : "l"(a), "l"(b));
    return d;
}
__device__ __forceinline__ float f2lo(unsigned long long x) {
    return __uint_as_float((unsigned int)x);
}
__device__ __forceinline__ float f2hi(unsigned long long x) {
    return __uint_as_float((unsigned int)(x >> 32));
}
__device__ __forceinline__ unsigned long long packf2(float lo, float hi) {
    return ((unsigned long long)__float_as_uint(hi) << 32) |
           (unsigned long long)__float_as_uint(lo);
}
__device__ __forceinline__ float sgnf(float x) {
    return (float)((x > 0.0f) - (x < 0.0f));
}

// ---------- init ----------
__global__ void init_kernel(const float* __restrict__ Binit) {
    int i = blockIdx.x * blockDim.x + threadIdx.x;
    if (i <= N_ITERS) { g_best[i] = 0ull; g_count[i] = 0u; }
    if (i < D * K) {
        float b = Binit[i];
        g_P[i] = b;
        g_B[i] = b;     // iteration 1 loss sees raw P
        g_M[i] = 0.0f;
        g_V[i] = 0.0f;
    }
}

// ---------- heavy: partial[chunk][j] = sum_{i in chunk} |E[i,j] - (B A)[i,j]| ----------
// FIRST=true: reads fp32 E, also writes bf16 copy. FIRST=false: reads bf16 copy.
template <bool FIRST>
__global__ __launch_bounds__(HK_THREADS, 2)
void heavy_kernel(const float* __restrict__ E, const float* __restrict__ A) {
    __shared__ ulonglong2 sB2[CHUNK_ROWS * (K / 2)];   // -B dup'd into both f32x2 lanes

    const int tile = blockIdx.x;
    const int chunk = blockIdx.y;
    const int tid = threadIdx.x;

    // load this chunk's B rows, negated + lane-duplicated (u64 layout r*K+k)
    {
        unsigned long long* sB = reinterpret_cast<unsigned long long*>(sB2);
        for (int idx = tid; idx < CHUNK_ROWS * K; idx += HK_THREADS) {
            int r = idx >> 4;
            int k = idx & 15;
            float b = -g_B[(chunk * CHUNK_ROWS + r) * K + k];
            unsigned int ub = __float_as_uint(b);
            sB[idx] = ((unsigned long long)ub << 32) | (unsigned long long)ub;
        }
    }
    __syncthreads();

    const int j0 = tile * TILE_COLS + tid * CPT;
    if (j0 >= T) return;                 // tail tile; no further syncs

    // A[k, j0..j0+3] into registers (fp32, 16B aligned)
    unsigned long long a01[K], a23[K];
#pragma unroll
    for (int k = 0; k < K; k++) {
        ulonglong2 av = *reinterpret_cast<const ulonglong2*>(A + k * T + j0);
        a01[k] = av.x;
        a23[k] = av.y;
    }

    unsigned long long cs01 = 0ull, cs23 = 0ull;

#pragma unroll 4
    for (int r = 0; r < CHUNK_ROWS; r++) {
        const long long off = (long long)(chunk * CHUNK_ROWS + r) * T + j0;
        unsigned long long acc01, acc23;
        if (FIRST) {
            float4 ev4 = *reinterpret_cast<const float4*>(E + off);
            acc01 = packf2(ev4.x, ev4.y);
            acc23 = packf2(ev4.z, ev4.w);
            unsigned int p01, p23;  // bf16 copy for later iterations (low half = first col)
            asm("cvt.rn.bf16x2.f32 %0, %1, %2;" : "=r"(p01) : "f"(ev4.y), "f"(ev4.x));
            asm("cvt.rn.bf16x2.f32 %0, %1, %2;" : "=r"(p23) : "f"(ev4.w), "f"(ev4.z));
            uint2 st; st.x = p01; st.y = p23;
            *reinterpret_cast<uint2*>(g_Ebf + off) = st;
        } else {
            uint2 ev = *reinterpret_cast<const uint2*>(g_Ebf + off);
            acc01 = ((unsigned long long)(ev.x & 0xFFFF0000u) << 32) |
                    (unsigned long long)(ev.x << 16);
            acc23 = ((unsigned long long)(ev.y & 0xFFFF0000u) << 32) |
                    (unsigned long long)(ev.y << 16);
        }
#pragma unroll
        for (int kk = 0; kk < K / 2; kk++) {
            ulonglong2 bb = sB2[r * (K / 2) + kk];
            acc01 = fma2(bb.x, a01[2 * kk], acc01);
            acc23 = fma2(bb.x, a23[2 * kk], acc23);
            acc01 = fma2(bb.y, a01[2 * kk + 1], acc01);
            acc23 = fma2(bb.y, a23[2 * kk + 1], acc23);
        }
        cs01 = add2(cs01, acc01 & 0x7FFFFFFF7FFFFFFFull);
        cs23 = add2(cs23, acc23 & 0x7FFFFFFF7FFFFFFFull);
    }

    float4 outp;
    outp.x = f2lo(cs01); outp.y = f2hi(cs01);
    outp.z = f2lo(cs23); outp.w = f2hi(cs23);
    *reinterpret_cast<float4*>(&g_part[chunk * T + j0]) = outp;
}

// ---------- argmax over columns + (last block) rank-1 gradient / Adam / shrink ----------
__global__ void argmax_update_kernel(const float* __restrict__ E,
                                     const float* __restrict__ A,
                                     float* __restrict__ outB, int it) {
    __shared__ unsigned long long warpmax[AX_THREADS / 32];
    __shared__ float sA[K];
    __shared__ float sColabs[K];
    __shared__ int sJstar, sKstar, sIsLast;

    const int tid = threadIdx.x;

    // Phase 0: sum partials, local argmax key
    unsigned long long best = 0ull;
    const int base = blockIdx.x * (AX_THREADS * AX_CPT);
#pragma unroll
    for (int c = 0; c < AX_CPT; c++) {
        int j = base + c * AX_THREADS + tid;    // coalesced
        if (j < T) {
            float s = 0.0f;
#pragma unroll
            for (int ch = 0; ch < NCHUNK; ch++) s += g_part[ch * T + j];
            // s >= 0 so float bits are order-preserving; tie-break toward smaller j
            unsigned long long key =
                ((unsigned long long)__float_as_uint(s) << 32) |
                (unsigned int)(T - 1 - j);
            if (key > best) best = key;
        }
    }
#pragma unroll
    for (int o = 16; o; o >>= 1) {
        unsigned long long other = __shfl_down_sync(0xffffffffu, best, o);
        if (other > best) best = other;
    }
    if ((tid & 31) == 0) warpmax[tid >> 5] = best;
    __syncthreads();
    if (tid == 0) {
        unsigned long long b = warpmax[0];
#pragma unroll
        for (int w = 1; w < AX_THREADS / 32; w++)
            if (warpmax[w] > b) b = warpmax[w];
        atomicMax(&g_best[it], b);
        __threadfence();
        unsigned int old = atomicAdd(&g_count[it], 1u);
        sIsLast = (old == AX_BLOCKS - 1);
    }
    __syncthreads();
    if (!sIsLast) return;

    // Last block performs the parameter update
    __threadfence();
    if (tid == 0)
        sJstar = T - 1 - (int)(g_best[it] & 0xffffffffu);
    __syncthreads();
    const int jstar = sJstar;

    // stage A[:, j*]
    if (tid < K) sA[tid] = A[tid * T + jstar];

    // column abs-sums of B (16 warps, one column each)
    {
        int w = tid >> 5, lane = tid & 31;
        if (w < K) {
            float s = 0.0f;
            for (int i = lane; i < D; i += 32) s += fabsf(g_B[i * K + w]);
#pragma unroll
            for (int o = 16; o; o >>= 1) s += __shfl_down_sync(0xffffffffu, s, o);
            if (lane == 0) sColabs[w] = s;
        }
    }
    __syncthreads();
    if (tid == 0) {
        int ks = 0;
        float bv = sColabs[0];
#pragma unroll
        for (int k = 1; k < K; k++)
            if (sColabs[k] > bv) { bv = sColabs[k]; ks = k; }
        sKstar = ks;
    }

    // residual sign for row tid at column j* (exact fp32 from original E)
    float si = 0.0f;
    if (tid < D) {
        float r = E[(long long)tid * T + jstar];
#pragma unroll
        for (int k = 0; k < K; k++) r -= g_B[tid * K + k] * sA[k];
        si = sgnf(r);
    }
    __syncthreads();            // sKstar ready; g_B reads done before writes below
    const int kstar = sKstar;

    // gradient + shrink chain + Adam + new B = shrink(P)
    if (tid < D) {
        float tf = (float)it;
        float bc1 = 1.0f - powf(BETA1_F, tf);
        float bc2 = 1.0f - powf(BETA2_F, tf);
#pragma unroll
        for (int k = 0; k < K; k++) {
            int idx = tid * K + k;
            float bu = g_B[idx];
            float g = -si * sA[k];
            if (k == kstar) g += LAMBDA1_F * sgnf(bu);
            float p = g_P[idx];
            if (it >= 2) g *= sgnf(p) * sgnf(p - SHRINK_C);   // d shrink / dP
            float m = BETA1_F * g_M[idx] + ONE_M_B1 * g;
            float v = BETA2_F * g_V[idx] + ONE_M_B2 * g * g;
            g_M[idx] = m;
            g_V[idx] = v;
            float mh = m / bc1;
            float vh = v / bc2;
            p = p - LR_F * mh / (sqrtf(vh) + ADAM_EPS_F);
            g_P[idx] = p;
            float bn = sgnf(p) * fmaxf(0.0f, fabsf(p - SHRINK_C));
            g_B[idx] = bn;
            if (it == N_ITERS) outB[idx] = bn;
        }
    }
}

extern "C" void kernel_launch(void* const* d_in, const int* in_sizes, int n_in,
                              void* d_out, int out_size) {
    (void)in_sizes; (void)n_in; (void)out_size;
    const float* E  = (const float*)d_in[0];   // embedding (512, 50000)
    const float* B0 = (const float*)d_in[1];   // basis_init (512, 16)
    const float* A  = (const float*)d_in[2];   // activation_init (16, 50000)
    float* out = (float*)d_out;                // [shrink(P) (512x16) | A (16x50000)]

    // A is constant in the reference (optimizer_act never steps) — copy once
    cudaMemcpyAsync(out + D * K, (const void*)A, (size_t)K * T * sizeof(float),
                    cudaMemcpyDeviceToDevice);

    init_kernel<<<(D * K + 255) / 256, 256>>>(B0);

    dim3 grid(NTILE, NCHUNK);
    for (int it = 1; it <= N_ITERS; ++it) {
        if (it == 1)
            heavy_kernel<true><<<grid, HK_THREADS>>>(E, A);
        else
            heavy_kernel<false><<<grid, HK_THREADS>>>(E, A);
        argmax_update_kernel<<<AX_BLOCKS, AX_THREADS>>>(E, A, out, it);
    }
}

// round 12
// speedup vs baseline: 1.1589x; 1.0401x over previous
#include <cuda_runtime.h>
#include <cuda_bf16.h>

// Problem constants (fixed shapes per reference setup_inputs)
#define D 512
#define T 50000
#define K 16
#define N_ITERS 10

// Heavy-kernel tiling
#define HK_THREADS 256
#define CPT 4                       // columns per thread (2x f32x2 accumulators)
#define TILE_COLS (HK_THREADS*CPT)  // 1024
#define NTILE 49                    // ceil(50000/1024)
#define CHUNK_ROWS 64
#define NCHUNK 8                    // 8*64 = 512 rows
#define ROWS_REG 4                  // rows held in registers per inner block
#define NRB (CHUNK_ROWS/ROWS_REG)   // 16 row-blocks

// Argmax+update kernel
#define AX_THREADS 512
#define AX_CPT 2
#define AX_BLOCKS 50                // 50*512*2 = 51200 >= 50000

// Reference hyper-parameters
#define LAMBDA1_F 0.3366f
#define SHRINK_C ((float)(0.1 * 0.3366))        // LR*LAMBDA1
#define BETA1_F 0.9f
#define BETA2_F 0.999f
#define ONE_M_B1 ((float)(1.0 - 0.9))
#define ONE_M_B2 ((float)(1.0 - 0.999))
#define ADAM_EPS_F 1e-8f
#define LR_F 0.1f

#define ABS2_MASK 0x7FFFFFFF7FFFFFFFull

// Device-global scratch (no allocations allowed)
__device__ float g_B[D * K];      // B the loss sees (P for it=1, shrink(P) after)
__device__ float g_P[D * K];
__device__ float g_M[D * K];
__device__ float g_V[D * K];
__device__ float g_part[NCHUNK * T];              // per-chunk column partial sums
__device__ __nv_bfloat16 g_Ebf[(size_t)D * T];    // bf16 copy of E (iters 2..N)
__device__ unsigned long long g_best[N_ITERS + 1];
__device__ unsigned int g_count[N_ITERS + 1];

// ---------- f32x2 helpers ----------
__device__ __forceinline__ unsigned long long fma2(unsigned long long a,
                                                   unsigned long long b,
                                                   unsigned long long c) {
    unsigned long long d;
    asm("fma.rn.f32x2 %0, %1, %2, %3;" : "=l"(d) : "l"(a), "l"(b), "l"(c));
    return d;
}
__device__ __forceinline__ unsigned long long add2(unsigned long long a,
                                                   unsigned long long b) {
    unsigned long long d;
    asm("add.rn.f32x2 %0, %1, %2;" : "=l"(d) : "l"(a), "l"(b));
    return d;
}
__device__ __forceinline__ float f2lo(unsigned long long x) {
    return __uint_as_float((unsigned int)x);
}
__device__ __forceinline__ float f2hi(unsigned long long x) {
    return __uint_as_float((unsigned int)(x >> 32));
}
__device__ __forceinline__ unsigned long long packf2(float lo, float hi) {
    return ((unsigned long long)__float_as_uint(hi) << 32) |
           (unsigned long long)__float_as_uint(lo);
}
// bf16x2 (lo=col j, hi=col j+1) -> packed f32x2 via 2x PRMT
__device__ __forceinline__ unsigned long long bf2_to_f2(unsigned int u) {
    unsigned int lo = __byte_perm(u, 0, 0x1044);   // {0,0,b0,b1} = bf_lo << 16
    unsigned int hi = __byte_perm(u, 0, 0x3244);   // {0,0,b2,b3} = bf_hi << 16
    return ((unsigned long long)hi << 32) | lo;
}
__device__ __forceinline__ float sgnf(float x) {
    return (float)((x > 0.0f) - (x < 0.0f));
}

// ---------- init ----------
__global__ void init_kernel(const float* __restrict__ Binit) {
    int i = blockIdx.x * blockDim.x + threadIdx.x;
    if (i <= N_ITERS) { g_best[i] = 0ull; g_count[i] = 0u; }
    if (i < D * K) {
        float b = Binit[i];
        g_P[i] = b;
        g_B[i] = b;     // iteration 1 loss sees raw P
        g_M[i] = 0.0f;
        g_V[i] = 0.0f;
    }
}

// ---------- heavy: partial[chunk][j] = sum_{i in chunk} |E[i,j] - (B A)[i,j]| ----------
// FIRST=true: reads fp32 E, also writes bf16 copy. FIRST=false: reads bf16 copy.
template <bool FIRST>
__global__ __launch_bounds__(HK_THREADS, 2)
void heavy_kernel(const float* __restrict__ E, const float* __restrict__ A) {
    // Bt[k][r]: -B[chunk*64+r][k], lane-duplicated into both f32x2 halves (8 KB)
    __shared__ unsigned long long sBt[K * CHUNK_ROWS];

    const int tile = blockIdx.x;
    const int chunk = blockIdx.y;
    const int tid = threadIdx.x;

    for (int idx = tid; idx < K * CHUNK_ROWS; idx += HK_THREADS) {
        int k = idx & (K - 1);
        int r = idx >> 4;
        float b = -g_B[(chunk * CHUNK_ROWS + r) * K + k];
        unsigned int ub = __float_as_uint(b);
        sBt[k * CHUNK_ROWS + r] = ((unsigned long long)ub << 32) | (unsigned long long)ub;
    }
    __syncthreads();

    const int j0 = tile * TILE_COLS + tid * CPT;
    if (j0 >= T) return;                 // tail tile; no syncs after this point

    // A[k, j0..j0+3] into registers (fp32, 16B aligned)
    unsigned long long a01[K], a23[K];
#pragma unroll
    for (int k = 0; k < K; k++) {
        ulonglong2 av = *reinterpret_cast<const ulonglong2*>(A + k * T + j0);
        a01[k] = av.x;
        a23[k] = av.y;
    }

    unsigned long long cs01 = 0ull, cs23 = 0ull;
    const int row0 = chunk * CHUNK_ROWS;

    if (FIRST) {
        // fp32 E path (DRAM-bound once); also emit bf16 copy
#pragma unroll 1
        for (int rb = 0; rb < NRB; rb++) {
            unsigned long long acc01[ROWS_REG], acc23[ROWS_REG];
#pragma unroll
            for (int r = 0; r < ROWS_REG; r++) {
                long long off = (long long)(row0 + rb * ROWS_REG + r) * T + j0;
                float4 ev = *reinterpret_cast<const float4*>(E + off);
                acc01[r] = packf2(ev.x, ev.y);
                acc23[r] = packf2(ev.z, ev.w);
                unsigned int p01, p23;
                asm("cvt.rn.bf16x2.f32 %0, %1, %2;" : "=r"(p01) : "f"(ev.y), "f"(ev.x));
                asm("cvt.rn.bf16x2.f32 %0, %1, %2;" : "=r"(p23) : "f"(ev.w), "f"(ev.z));
                uint2 st; st.x = p01; st.y = p23;
                *reinterpret_cast<uint2*>(g_Ebf + off) = st;
            }
#pragma unroll
            for (int k = 0; k < K; k++) {
                const ulonglong2* bp =
                    reinterpret_cast<const ulonglong2*>(&sBt[k * CHUNK_ROWS + rb * ROWS_REG]);
                ulonglong2 b01 = bp[0], b23 = bp[1];
                acc01[0] = fma2(b01.x, a01[k], acc01[0]);
                acc23[0] = fma2(b01.x, a23[k], acc23[0]);
                acc01[1] = fma2(b01.y, a01[k], acc01[1]);
                acc23[1] = fma2(b01.y, a23[k], acc23[1]);
                acc01[2] = fma2(b23.x, a01[k], acc01[2]);
                acc23[2] = fma2(b23.x, a23[k], acc23[2]);
                acc01[3] = fma2(b23.y, a01[k], acc01[3]);
                acc23[3] = fma2(b23.y, a23[k], acc23[3]);
            }
#pragma unroll
            for (int r = 0; r < ROWS_REG; r++) {
                cs01 = add2(cs01, acc01[r] & ABS2_MASK);
                cs23 = add2(cs23, acc23[r] & ABS2_MASK);
            }
        }
    } else {
        // bf16 E path: double-buffered loads so L2 latency hides behind the k-loop
        uint2 e[ROWS_REG], en[ROWS_REG];
#pragma unroll
        for (int r = 0; r < ROWS_REG; r++)
            e[r] = *reinterpret_cast<const uint2*>(
                g_Ebf + (long long)(row0 + r) * T + j0);

#pragma unroll 1
        for (int rb = 0; rb < NRB; rb++) {
            if (rb + 1 < NRB) {
#pragma unroll
                for (int r = 0; r < ROWS_REG; r++)
                    en[r] = *reinterpret_cast<const uint2*>(
                        g_Ebf + (long long)(row0 + (rb + 1) * ROWS_REG + r) * T + j0);
            }

            unsigned long long acc01[ROWS_REG], acc23[ROWS_REG];
#pragma unroll
            for (int r = 0; r < ROWS_REG; r++) {
                acc01[r] = bf2_to_f2(e[r].x);
                acc23[r] = bf2_to_f2(e[r].y);
            }
#pragma unroll
            for (int k = 0; k < K; k++) {
                const ulonglong2* bp =
                    reinterpret_cast<const ulonglong2*>(&sBt[k * CHUNK_ROWS + rb * ROWS_REG]);
                ulonglong2 b01 = bp[0], b23 = bp[1];
                acc01[0] = fma2(b01.x, a01[k], acc01[0]);
                acc23[0] = fma2(b01.x, a23[k], acc23[0]);
                acc01[1] = fma2(b01.y, a01[k], acc01[1]);
                acc23[1] = fma2(b01.y, a23[k], acc23[1]);
                acc01[2] = fma2(b23.x, a01[k], acc01[2]);
                acc23[2] = fma2(b23.x, a23[k], acc23[2]);
                acc01[3] = fma2(b23.y, a01[k], acc01[3]);
                acc23[3] = fma2(b23.y, a23[k], acc23[3]);
            }
#pragma unroll
            for (int r = 0; r < ROWS_REG; r++) {
                cs01 = add2(cs01, acc01[r] & ABS2_MASK);
                cs23 = add2(cs23, acc23[r] & ABS2_MASK);
                e[r] = en[r];
            }
        }
    }

    float4 outp;
    outp.x = f2lo(cs01); outp.y = f2hi(cs01);
    outp.z = f2lo(cs23); outp.w = f2hi(cs23);
    *reinterpret_cast<float4*>(&g_part[chunk * T + j0]) = outp;
}

// ---------- argmax over columns + (last block) rank-1 gradient / Adam / shrink ----------
__global__ void argmax_update_kernel(const float* __restrict__ E,
                                     const float* __restrict__ A,
                                     float* __restrict__ outB, int it) {
    __shared__ unsigned long long warpmax[AX_THREADS / 32];
    __shared__ float sA[K];
    __shared__ float sColabs[K];
    __shared__ int sJstar, sKstar, sIsLast;

    const int tid = threadIdx.x;

    // Phase 0: sum partials, local argmax key
    unsigned long long best = 0ull;
    const int base = blockIdx.x * (AX_THREADS * AX_CPT);
#pragma unroll
    for (int c = 0; c < AX_CPT; c++) {
        int j = base + c * AX_THREADS + tid;    // coalesced
        if (j < T) {
            float s = 0.0f;
#pragma unroll
            for (int ch = 0; ch < NCHUNK; ch++) s += g_part[ch * T + j];
            // s >= 0 so float bits are order-preserving; tie-break toward smaller j
            unsigned long long key =
                ((unsigned long long)__float_as_uint(s) << 32) |
                (unsigned int)(T - 1 - j);
            if (key > best) best = key;
        }
    }
#pragma unroll
    for (int o = 16; o; o >>= 1) {
        unsigned long long other = __shfl_down_sync(0xffffffffu, best, o);
        if (other > best) best = other;
    }
    if ((tid & 31) == 0) warpmax[tid >> 5] = best;
    __syncthreads();
    if (tid == 0) {
        unsigned long long b = warpmax[0];
#pragma unroll
        for (int w = 1; w < AX_THREADS / 32; w++)
            if (warpmax[w] > b) b = warpmax[w];
        atomicMax(&g_best[it], b);
        __threadfence();
        unsigned int old = atomicAdd(&g_count[it], 1u);
        sIsLast = (old == AX_BLOCKS - 1);
    }
    __syncthreads();
    if (!sIsLast) return;

    // Last block performs the parameter update
    __threadfence();
    if (tid == 0)
        sJstar = T - 1 - (int)(g_best[it] & 0xffffffffu);
    __syncthreads();
    const int jstar = sJstar;

    // stage A[:, j*]
    if (tid < K) sA[tid] = A[tid * T + jstar];

    // column abs-sums of B (16 warps, one column each)
    {
        int w = tid >> 5, lane = tid & 31;
        if (w < K) {
            float s = 0.0f;
            for (int i = lane; i < D; i += 32) s += fabsf(g_B[i * K + w]);
#pragma unroll
            for (int o = 16; o; o >>= 1) s += __shfl_down_sync(0xffffffffu, s, o);
            if (lane == 0) sColabs[w] = s;
        }
    }
    __syncthreads();
    if (tid == 0) {
        int ks = 0;
        float bv = sColabs[0];
#pragma unroll
        for (int k = 1; k < K; k++)
            if (sColabs[k] > bv) { bv = sColabs[k]; ks = k; }
        sKstar = ks;
    }

    // residual sign for row tid at column j* (exact fp32 from original E)
    float si = 0.0f;
    if (tid < D) {
        float r = E[(long long)tid * T + jstar];
#pragma unroll
        for (int k = 0; k < K; k++) r -= g_B[tid * K + k] * sA[k];
        si = sgnf(r);
    }
    __syncthreads();            // sKstar ready; g_B reads done before writes below
    const int kstar = sKstar;

    // gradient + shrink chain + Adam + new B = shrink(P)
    if (tid < D) {
        float tf = (float)it;
        float bc1 = 1.0f - powf(BETA1_F, tf);
        float bc2 = 1.0f - powf(BETA2_F, tf);
#pragma unroll
        for (int k = 0; k < K; k++) {
            int idx = tid * K + k;
            float bu = g_B[idx];
            float g = -si * sA[k];
            if (k == kstar) g += LAMBDA1_F * sgnf(bu);
            float p = g_P[idx];
            if (it >= 2) g *= sgnf(p) * sgnf(p - SHRINK_C);   // d shrink / dP
            float m = BETA1_F * g_M[idx] + ONE_M_B1 * g;
            float v = BETA2_F * g_V[idx] + ONE_M_B2 * g * g;
            g_M[idx] = m;
            g_V[idx] = v;
            float mh = m / bc1;
            float vh = v / bc2;
            p = p - LR_F * mh / (sqrtf(vh) + ADAM_EPS_F);
            g_P[idx] = p;
            float bn = sgnf(p) * fmaxf(0.0f, fabsf(p - SHRINK_C));
            g_B[idx] = bn;
            if (it == N_ITERS) outB[idx] = bn;
        }
    }
}

extern "C" void kernel_launch(void* const* d_in, const int* in_sizes, int n_in,
                              void* d_out, int out_size) {
    (void)in_sizes; (void)n_in; (void)out_size;
    const float* E  = (const float*)d_in[0];   // embedding (512, 50000)
    const float* B0 = (const float*)d_in[1];   // basis_init (512, 16)
    const float* A  = (const float*)d_in[2];   // activation_init (16, 50000)
    float* out = (float*)d_out;                // [shrink(P) (512x16) | A (16x50000)]

    // A is constant in the reference (optimizer_act never steps) — copy once
    cudaMemcpyAsync(out + D * K, (const void*)A, (size_t)K * T * sizeof(float),
                    cudaMemcpyDeviceToDevice);

    init_kernel<<<(D * K + 255) / 256, 256>>>(B0);

    dim3 grid(NTILE, NCHUNK);
    for (int it = 1; it <= N_ITERS; ++it) {
        if (it == 1)
            heavy_kernel<true><<<grid, HK_THREADS>>>(E, A);
        else
            heavy_kernel<false><<<grid, HK_THREADS>>>(E, A);
        argmax_update_kernel<<<AX_BLOCKS, AX_THREADS>>>(E, A, out, it);
    }
}